// round 5
// baseline (speedup 1.0000x reference)
#include <cuda_runtime.h>
#include <cstddef>

#define NN 2048
#define EE 32
#define R2F 0.0025f          // float32(0.05^2), matches JAX scalar promotion
#define ROWS_PER_BLK 4
#define NBLOCKS (NN / ROWS_PER_BLK)   // 512 -> single co-resident wave

// Rare path: 2-layer MLP for one valid edge; this lane produces output
// features [4*eb, 4*eb+4). Weights pre-staged in shared memory as float4.
__device__ __noinline__ float4 edge_mlp(float rx, float ry,
                                        const float4* __restrict__ sW1p,
                                        const float4* __restrict__ sW2,
                                        const float4* __restrict__ sb2,
                                        int eb) {
    float4 acc = sb2[eb];
#pragma unroll 8
    for (int j = 0; j < 32; j++) {
        float4 w1 = sW1p[j];                         // {W1[0][j], W1[1][j], b1[j], 0}
        float h = fmaf(ry, w1.y, fmaf(rx, w1.x, w1.z));
        h = fmaxf(h, 0.0f);
        float4 w2 = sW2[j * 8 + eb];                 // W2[j][4eb .. 4eb+3]
        acc.x = fmaf(h, w2.x, acc.x);
        acc.y = fmaf(h, w2.y, acc.y);
        acc.z = fmaf(h, w2.z, acc.z);
        acc.w = fmaf(h, w2.w, acc.w);
    }
    return acc;
}

// Block = 256 threads = 8 warps; block owns ROWS_PER_BLK contiguous source
// rows (1MiB contiguous output). Per row, warp w handles 32-dst chunks
// c = w, w+8, ...; one ballot per chunk gates the zero fast path (~78%).
__global__ void __launch_bounds__(256)
graph_edges_kernel(const float* __restrict__ pos,
                   const float* __restrict__ W1,
                   const float* __restrict__ b1,
                   const float* __restrict__ W2,
                   const float* __restrict__ b2,
                   float4* __restrict__ out) {
    __shared__ float4 sW1p[32];    // packed {W1x, W1y, b1, 0}
    __shared__ float4 sW2[256];    // W2[32][32] as 32 rows x 8 float4
    __shared__ float4 sb2[8];

    const int tid = threadIdx.x;
    if (tid < 32) sW1p[tid] = make_float4(W1[tid], W1[32 + tid], b1[tid], 0.0f);
    sW2[tid] = ((const float4*)W2)[tid];             // 256 float4 = 1024 floats
    if (tid < 8) sb2[tid] = ((const float4*)b2)[tid];
    __syncthreads();

    const int lane = tid & 31;
    const int warp = tid >> 5;
    const int grp  = lane >> 3;    // which of 4 pairs in a store iteration
    const int eb   = lane & 7;     // which float4 of the 32 features
    const float2* pos2 = (const float2*)pos;
    const float4 zero4 = make_float4(0.0f, 0.0f, 0.0f, 0.0f);

#pragma unroll 1
    for (int r = 0; r < ROWS_PER_BLK; r++) {
        const int s = blockIdx.x * ROWS_PER_BLK + r;
        const float2 ps = pos2[s];

#pragma unroll 1
        for (int c = warp; c < NN / 32; c += 8) {
            const int d0 = c * 32;
            const float2 pd = pos2[d0 + lane];
            const float rx = pd.x - ps.x;            // pos[dst] - pos[src]
            const float ry = pd.y - ps.y;
            // no-FMA dist2: bit-exact with jnp (mul, mul, add in f32)
            const float d2 = __fadd_rn(__fmul_rn(rx, rx), __fmul_rn(ry, ry));
            const bool myvalid = (d2 <= R2F) && ((d0 + lane) != s);
            const unsigned mask = __ballot_sync(0xffffffffu, myvalid);

            float4* o = out + ((size_t)s * NN + (size_t)d0) * (EE / 4);

            if (mask == 0u) {
                // ~78% of chunks: 8 back-to-back coalesced STG.128, no ALU.
#pragma unroll
                for (int i = 0; i < 8; i++)
                    o[i * 32 + lane] = zero4;
            } else {
#pragma unroll 1
                for (int i = 0; i < 8; i++) {
                    const unsigned m4 = (mask >> (i * 4)) & 0xFu;  // uniform
                    float4 v = zero4;
                    if (m4) {
                        const int src = i * 4 + grp;
                        const float frx = __shfl_sync(0xffffffffu, rx, src);
                        const float fry = __shfl_sync(0xffffffffu, ry, src);
                        if ((m4 >> grp) & 1u)
                            v = edge_mlp(frx, fry, sW1p, sW2, sb2, eb);
                    }
                    o[i * 32 + lane] = v;            // 512B/warp coalesced
                }
            }
        }
    }
}

// Inputs (metadata order): node_features (unused), object_positions_2d,
// W1, b1, W2, b2. Output: edge_attr [N, N, E] fp32.
extern "C" void kernel_launch(void* const* d_in, const int* in_sizes, int n_in,
                              void* d_out, int out_size) {
    const float* pos = (const float*)d_in[1];
    const float* W1  = (const float*)d_in[2];
    const float* b1  = (const float*)d_in[3];
    const float* W2  = (const float*)d_in[4];
    const float* b2  = (const float*)d_in[5];
    graph_edges_kernel<<<NBLOCKS, 256>>>(pos, W1, b1, W2, b2, (float4*)d_out);
}

// round 6
// speedup vs baseline: 1.2439x; 1.2439x over previous
#include <cuda_runtime.h>
#include <cstddef>

#define NN 2048
#define EE 32
#define R2F 0.0025f   // float32(0.05^2), matches JAX's weak-typed scalar promotion

// Rare path: 2-layer MLP for one valid edge; this lane produces output
// features [4*eb, 4*eb+4). Weights pre-staged in shared memory as float4.
// __noinline__ keeps the hot store loop small (I$); taken for ~3% of iters.
__device__ __noinline__ float4 edge_mlp(float rx, float ry,
                                        const float4* __restrict__ sW1p,
                                        const float4* __restrict__ sW2,
                                        const float4* __restrict__ sb2,
                                        int eb) {
    float4 acc = sb2[eb];
#pragma unroll 8
    for (int j = 0; j < 32; j++) {
        float4 w1 = sW1p[j];                         // {W1[0][j], W1[1][j], b1[j], 0}
        float h = fmaf(ry, w1.y, fmaf(rx, w1.x, w1.z));
        h = fmaxf(h, 0.0f);
        float4 w2 = sW2[j * 8 + eb];                 // W2[j][4eb .. 4eb+3]
        acc.x = fmaf(h, w2.x, acc.x);
        acc.y = fmaf(h, w2.y, acc.y);
        acc.z = fmaf(h, w2.z, acc.z);
        acc.w = fmaf(h, w2.w, acc.w);
    }
    return acc;
}

// Grid = 4096: block b handles source row s = b>>1, half = b&1 (32 of the 64
// 32-dst chunks). 256 threads = 8 warps; warp w takes chunks half*32 + w,
// +8, +16, +24. Inner loop identical to the best-measured R1 kernel:
// per-iteration shuffle redistribution, predicated rare-path MLP, plain
// coalesced STG.128 (512B per warp store iteration).
__global__ void __launch_bounds__(256)
graph_edges_kernel(const float* __restrict__ pos,
                   const float* __restrict__ W1,
                   const float* __restrict__ b1,
                   const float* __restrict__ W2,
                   const float* __restrict__ b2,
                   float4* __restrict__ out) {
    __shared__ float4 sW1p[32];    // packed {W1x, W1y, b1, 0}
    __shared__ float4 sW2[256];    // W2[32][32] as 32 rows x 8 float4
    __shared__ float4 sb2[8];

    const int tid = threadIdx.x;
    if (tid < 32) sW1p[tid] = make_float4(W1[tid], W1[32 + tid], b1[tid], 0.0f);
    sW2[tid] = ((const float4*)W2)[tid];             // 256 float4 = 1024 floats
    if (tid < 8) sb2[tid] = ((const float4*)b2)[tid];
    __syncthreads();

    const int lane = tid & 31;
    const int warp = tid >> 5;
    const int grp  = lane >> 3;    // which of 4 pairs in a store iteration
    const int eb   = lane & 7;     // which float4 of the 32 features
    const int s    = blockIdx.x >> 1;
    const int c0   = (blockIdx.x & 1) * 32;          // this block's chunk range

    const float2 ps = ((const float2*)pos)[s];

#pragma unroll 1
    for (int cc = warp; cc < 32; cc += 8) {
        const int c = c0 + cc;
        const int d0 = c * 32;
        const float2 pd = ((const float2*)pos)[d0 + lane];
        const float rx = pd.x - ps.x;    // pos[dst] - pos[src], matches reference
        const float ry = pd.y - ps.y;

        const size_t base = ((size_t)s * NN + (size_t)d0) * (EE / 4);

#pragma unroll 1
        for (int i = 0; i < 8; i++) {
            const int src = i * 4 + grp;                 // lane owning my pair's rel_pos
            const float frx = __shfl_sync(0xffffffffu, rx, src);
            const float fry = __shfl_sync(0xffffffffu, ry, src);
            // no-FMA dist2: bit-exact with jnp (mul, mul, add in f32)
            const float d2 = __fadd_rn(__fmul_rn(frx, frx), __fmul_rn(fry, fry));
            const bool valid = (d2 <= R2F) && ((d0 + src) != s);

            float4 v = make_float4(0.0f, 0.0f, 0.0f, 0.0f);
            if (valid) v = edge_mlp(frx, fry, sW1p, sW2, sb2, eb);

            out[base + (size_t)i * 32 + lane] = v;       // 512B/warp, coalesced
        }
    }
}

// Inputs (metadata order): node_features (unused), object_positions_2d,
// W1, b1, W2, b2. Output: edge_attr [N, N, E] fp32.
extern "C" void kernel_launch(void* const* d_in, const int* in_sizes, int n_in,
                              void* d_out, int out_size) {
    const float* pos = (const float*)d_in[1];
    const float* W1  = (const float*)d_in[2];
    const float* b1  = (const float*)d_in[3];
    const float* W2  = (const float*)d_in[4];
    const float* b2  = (const float*)d_in[5];
    graph_edges_kernel<<<NN * 2, 256>>>(pos, W1, b1, W2, b2, (float4*)d_out);
}

// round 7
// speedup vs baseline: 1.2772x; 1.0268x over previous
#include <cuda_runtime.h>
#include <cstddef>

#define NN 2048
#define EE 32
#define R2F 0.0025f   // float32(0.05^2), matches JAX's weak-typed scalar promotion
#define SPLIT 4       // blocks per source row
#define CHUNKS_PER_BLK (64 / SPLIT)   // 16 x 32-dst chunks

// Rare path: 2-layer MLP for one valid edge; this lane produces output
// features [4*eb, 4*eb+4). Weights pre-staged in shared memory as float4.
// __noinline__ keeps the hot store loop small (I$); taken for ~3% of iters.
__device__ __noinline__ float4 edge_mlp(float rx, float ry,
                                        const float4* __restrict__ sW1p,
                                        const float4* __restrict__ sW2,
                                        const float4* __restrict__ sb2,
                                        int eb) {
    float4 acc = sb2[eb];
#pragma unroll 8
    for (int j = 0; j < 32; j++) {
        float4 w1 = sW1p[j];                         // {W1[0][j], W1[1][j], b1[j], 0}
        float h = fmaf(ry, w1.y, fmaf(rx, w1.x, w1.z));
        h = fmaxf(h, 0.0f);
        float4 w2 = sW2[j * 8 + eb];                 // W2[j][4eb .. 4eb+3]
        acc.x = fmaf(h, w2.x, acc.x);
        acc.y = fmaf(h, w2.y, acc.y);
        acc.z = fmaf(h, w2.z, acc.z);
        acc.w = fmaf(h, w2.w, acc.w);
    }
    return acc;
}

// Grid = 8192: block b handles source row s = b/SPLIT, quarter q = b%SPLIT
// (16 of the 64 32-dst chunks). 256 threads = 8 warps; warp w takes chunks
// q*16 + w, q*16 + w + 8. Inner loop = best-measured R1/R6 form: shuffle
// redistribution, predicated rare-path MLP, plain coalesced STG.128.
__global__ void __launch_bounds__(256)
graph_edges_kernel(const float* __restrict__ pos,
                   const float* __restrict__ W1,
                   const float* __restrict__ b1,
                   const float* __restrict__ W2,
                   const float* __restrict__ b2,
                   float4* __restrict__ out) {
    __shared__ float4 sW1p[32];    // packed {W1x, W1y, b1, 0}
    __shared__ float4 sW2[256];    // W2[32][32] as 32 rows x 8 float4
    __shared__ float4 sb2[8];

    const int tid = threadIdx.x;
    if (tid < 32) sW1p[tid] = make_float4(W1[tid], W1[32 + tid], b1[tid], 0.0f);
    sW2[tid] = ((const float4*)W2)[tid];             // 256 float4 = 1024 floats
    if (tid < 8) sb2[tid] = ((const float4*)b2)[tid];
    __syncthreads();

    const int lane = tid & 31;
    const int warp = tid >> 5;
    const int grp  = lane >> 3;    // which of 4 pairs in a store iteration
    const int eb   = lane & 7;     // which float4 of the 32 features
    const int s    = blockIdx.x / SPLIT;
    const int c0   = (blockIdx.x % SPLIT) * CHUNKS_PER_BLK;

    const float2 ps = ((const float2*)pos)[s];

#pragma unroll 1
    for (int cc = warp; cc < CHUNKS_PER_BLK; cc += 8) {
        const int d0 = (c0 + cc) * 32;
        const float2 pd = ((const float2*)pos)[d0 + lane];
        const float rx = pd.x - ps.x;    // pos[dst] - pos[src], matches reference
        const float ry = pd.y - ps.y;

        const size_t base = ((size_t)s * NN + (size_t)d0) * (EE / 4);

#pragma unroll 1
        for (int i = 0; i < 8; i++) {
            const int src = i * 4 + grp;                 // lane owning my pair's rel_pos
            const float frx = __shfl_sync(0xffffffffu, rx, src);
            const float fry = __shfl_sync(0xffffffffu, ry, src);
            // no-FMA dist2: bit-exact with jnp (mul, mul, add in f32)
            const float d2 = __fadd_rn(__fmul_rn(frx, frx), __fmul_rn(fry, fry));
            const bool valid = (d2 <= R2F) && ((d0 + src) != s);

            float4 v = make_float4(0.0f, 0.0f, 0.0f, 0.0f);
            if (valid) v = edge_mlp(frx, fry, sW1p, sW2, sb2, eb);

            out[base + (size_t)i * 32 + lane] = v;       // 512B/warp, coalesced
        }
    }
}

// Inputs (metadata order): node_features (unused), object_positions_2d,
// W1, b1, W2, b2. Output: edge_attr [N, N, E] fp32.
extern "C" void kernel_launch(void* const* d_in, const int* in_sizes, int n_in,
                              void* d_out, int out_size) {
    const float* pos = (const float*)d_in[1];
    const float* W1  = (const float*)d_in[2];
    const float* b1  = (const float*)d_in[3];
    const float* W2  = (const float*)d_in[4];
    const float* b2  = (const float*)d_in[5];
    graph_edges_kernel<<<NN * SPLIT, 256>>>(pos, W1, b1, W2, b2, (float4*)d_out);
}